// round 3
// baseline (speedup 1.0000x reference)
#include <cuda_runtime.h>
#include <cfloat>
#include <math.h>

#define BB   4
#define LL   2048
#define NODES (BB*LL)            // 8192
#define TOPK 30
#define NEDGE (NODES*TOPK)       // 245760

// ---------------- scratch ----------------------------------------------------
__device__ float4 g_CaP[NODES];
__device__ float4 g_E1[NODES];
__device__ float4 g_E2[NODES];
__device__ float4 g_E3[NODES];
__device__ float  g_Dnb[NEDGE];
__device__ int    g_Eidx[NEDGE];
__device__ float  g_Ppe[65*128];           // (W_pe+b_pe) @ W_edge[0:16]
__device__ float  g_Pch[2*128];            // (W_ch+b_ch) @ W_edge[39:55]
__device__ float  g_W2r[23*128];           // W_edge rows [16:39)

__device__ __forceinline__ float signf_(float x){ return (x>0.f)?1.f:((x<0.f)?-1.f:0.f); }

#define FMA2(d,a,b,c) asm("fma.rn.f32x2 %0,%1,%2,%3;" : "=l"(d) : "l"(a), "l"(b), "l"(c))
#define ADD2(d,a,b)   asm("add.rn.f32x2 %0,%1,%2;"    : "=l"(d) : "l"(a), "l"(b))
#define MUL2(d,a,b)   asm("mul.rn.f32x2 %0,%1,%2;"    : "=l"(d) : "l"(a), "l"(b))
#define PACK2(d,lo,hi) asm("mov.b64 %0,{%1,%2};" : "=l"(d) : "f"(lo), "f"(hi))
#define UNPK2(lo,hi,s) asm("mov.b64 {%0,%1},%2;" : "=f"(lo), "=f"(hi) : "l"(s))

// ---------------- kernel 1: prep (pack frames + projection tables) ----------
__global__ void k_prep(const float* __restrict__ X,
                       const float* __restrict__ W_pe, const float* __restrict__ b_pe,
                       const float* __restrict__ W_ch, const float* __restrict__ b_ch,
                       const float* __restrict__ W_edge){
    int blk = blockIdx.x;
    if (blk < 32){
        int n = blk*256 + threadIdx.x;
        const float* p = X + (size_t)n*12;
        float Nx=p[0], Ny=p[1], Nz=p[2];
        float Cx=p[3], Cy=p[4], Cz=p[5];
        float Dx=p[6], Dy=p[7], Dz=p[8];
        g_CaP[n] = make_float4(Cx,Cy,Cz,0.f);
        float v1x=Nx-Cx, v1y=Ny-Cy, v1z=Nz-Cz;
        float v2x=Dx-Cx, v2y=Dy-Cy, v2z=Dz-Cz;
        float n1 = sqrtf(v1x*v1x+v1y*v1y+v1z*v1z);
        float i1 = 1.f/(n1+1e-6f);
        float e1x=v1x*i1, e1y=v1y*i1, e1z=v1z*i1;
        float dv = e1x*v2x+e1y*v2y+e1z*v2z;
        float u2x=v2x-dv*e1x, u2y=v2y-dv*e1y, u2z=v2z-dv*e1z;
        float n2 = sqrtf(u2x*u2x+u2y*u2y+u2z*u2z);
        float i2 = 1.f/(n2+1e-6f);
        float e2x=u2x*i2, e2y=u2y*i2, e2z=u2z*i2;
        g_E1[n] = make_float4(e1x,e1y,e1z,0.f);
        g_E2[n] = make_float4(e2x,e2y,e2z,0.f);
        g_E3[n] = make_float4(e1y*e2z-e1z*e2y, e1z*e2x-e1x*e2z, e1x*e2y-e1y*e2x, 0.f);
    } else {
        int idx = (blk-32)*256 + threadIdx.x;
        if (idx < 65*128){
            int r = idx >> 7, c = idx & 127;
            float s = 0.f;
            #pragma unroll
            for (int m=0;m<16;m++) s += (W_pe[r*16+m]+b_pe[m]) * W_edge[m*128+c];
            g_Ppe[idx] = s;
        } else if (idx < 65*128 + 2*128){
            int t = idx - 65*128; int r = t >> 7, c = t & 127;
            float s = 0.f;
            #pragma unroll
            for (int m=0;m<16;m++) s += (W_ch[r*16+m]+b_ch[m]) * W_edge[(39+m)*128+c];
            g_Pch[t] = s;
        } else if (idx < 65*128 + 2*128 + 23*128){
            int t = idx - (65*128+2*128); int r = t >> 7, c = t & 127;
            int row = (r < 16) ? (16+r) : (32 + (r-16));
            g_W2r[t] = W_edge[row*128+c];
        }
    }
}

// ---------------- kernel 2: top-30 per row via radix select -----------------
__global__ void k_topk(float* __restrict__ outIdxF){
    __shared__ unsigned sK[2048];
    __shared__ unsigned sCnt[256];
    __shared__ unsigned sTieJ[256];
    __shared__ unsigned sWinK[32];
    __shared__ unsigned sWinJ[32];
    __shared__ unsigned sCtl[4];   // 0: prefix, 1: base, 2: cntL, 3: cntE

    int row = blockIdx.x;
    int b   = row >> 11;
    int tid = threadIdx.x;         // 512 threads
    int lane = tid & 31;
    float4 p = g_CaP[row];

    #pragma unroll
    for (int u=0;u<4;u++){
        int j = tid + (u<<9);
        float4 q = g_CaP[(b<<11)+j];
        float dx=q.x-p.x, dy=q.y-p.y, dz=q.z-p.z;
        float s = __fadd_rn(__fadd_rn(__fmul_rn(dx,dx),__fmul_rn(dy,dy)),__fmul_rn(dz,dz));
        float D = __fsqrt_rn(__fadd_rn(s, 1e-6f));
        sK[j] = __float_as_uint(D);
    }
    if (tid < 4) sCtl[tid] = 0;
    if (tid < 256) sCnt[tid] = 0;
    __syncthreads();

    #pragma unroll
    for (int pass=0; pass<4; pass++){
        int shift = 24 - 8*pass;
        unsigned pref = sCtl[0];
        #pragma unroll
        for (int u=0;u<4;u++){
            unsigned k = sK[tid + (u<<9)];
            bool act = ( ((unsigned long long)(k ^ pref) >> (shift+8)) == 0ULL );
            unsigned bin = (k>>shift)&255u;
            // warp-aggregated histogram: leaders add popc
            unsigned v = act ? bin : (0x100u | (unsigned)lane);
            unsigned grp = __match_any_sync(0xffffffffu, v);
            if (act && ((__ffs(grp)-1) == lane))
                atomicAdd(&sCnt[bin], __popc(grp));
        }
        __syncthreads();
        if (tid < 32){
            unsigned c[8]; unsigned s = 0;
            #pragma unroll
            for (int i=0;i<8;i++){ c[i] = sCnt[tid*8+i]; s += c[i]; }
            unsigned incl = s;
            #pragma unroll
            for (int off=1; off<32; off<<=1){
                unsigned v = __shfl_up_sync(0xffffffffu, incl, off);
                if (tid >= off) incl += v;
            }
            unsigned excl = incl - s;
            unsigned base = sCtl[1];
            unsigned need = 29u - base;
            if (need >= excl && need < incl){
                unsigned acc = excl; int bsel = -1; unsigned basebin = excl;
                #pragma unroll
                for (int i=0;i<8;i++){
                    if (bsel < 0){
                        if (need < acc + c[i]) { bsel = i; basebin = acc; }
                        else acc += c[i];
                    }
                }
                sCtl[0] = pref | ((unsigned)(tid*8 + bsel) << shift);
                sCtl[1] = base + basebin;
            }
        }
        __syncthreads();
        if (tid < 256) sCnt[tid] = 0;   // reset for next pass (no extra barrier needed
        __syncthreads();                //  before use: barrier here)
    }

    unsigned P = sCtl[0];
    #pragma unroll
    for (int u=0;u<4;u++){
        int j = tid + (u<<9);
        unsigned k = sK[j];
        if (k < P){
            unsigned pos = atomicAdd(&sCtl[2], 1u);
            sWinK[pos] = k; sWinJ[pos] = (unsigned)j;
        } else if (k == P){
            unsigned pos = atomicAdd(&sCtl[3], 1u);
            if (pos < 256) sTieJ[pos] = (unsigned)j;
        }
    }
    __syncthreads();
    unsigned cntL = sCtl[2];
    unsigned cntE = sCtl[3];
    unsigned needE = 30u - cntL;
    if (tid < (int)cntE && tid < 256){
        unsigned myj = sTieJ[tid];
        unsigned r = 0;
        unsigned lim = (cntE < 256u) ? cntE : 256u;
        for (unsigned i=0;i<lim;i++) r += (sTieJ[i] < myj) ? 1u : 0u;
        if (r < needE){ sWinK[cntL + r] = P; sWinJ[cntL + r] = myj; }
    }
    __syncthreads();
    unsigned mk=0, mj=0, rk=0;
    if (tid < (int)cntL){
        mk = sWinK[tid]; mj = sWinJ[tid];
        for (unsigned i=0;i<cntL;i++){
            unsigned ok = sWinK[i], oj = sWinJ[i];
            rk += ((ok < mk) || (ok == mk && oj < mj)) ? 1u : 0u;
        }
    }
    __syncthreads();
    if (tid < (int)cntL){ sWinK[rk] = mk; sWinJ[rk] = mj; }
    __syncthreads();
    if (tid < TOPK){
        int e = row*TOPK + tid;
        unsigned j = sWinJ[tid];
        g_Eidx[e]  = (int)j;
        g_Dnb[e]   = __uint_as_float(sWinK[tid]);
        outIdxF[e] = (float)j;
    }
}

// ---------------- kernel 3: node dihedral features + LN (warp/node) ---------
// trig-free: cosA is the dot; sinA=sqrt(1-cosA^2); sinD=sign*sqrt(1-cosD^2)
__global__ void k_node(const float* __restrict__ W_node, const float* __restrict__ b_node,
                       const float* __restrict__ gN, const float* __restrict__ bnN,
                       float* __restrict__ outV){
    int gw   = (blockIdx.x*blockDim.x + threadIdx.x) >> 5;
    int lane = threadIdx.x & 31;
    if (gw >= NODES) return;
    int l = gw & 2047;

    float ad0=0.f, ad1=0.f, ad2=0.f;
    if (l >= 1 && l <= LL-3){
        float4 p0=g_CaP[gw-1], p1=g_CaP[gw], p2=g_CaP[gw+1], p3=g_CaP[gw+2];
        float ax=p1.x-p0.x, ay=p1.y-p0.y, az=p1.z-p0.z;
        float bx=p2.x-p1.x, by=p2.y-p1.y, bz=p2.z-p1.z;
        float cx=p3.x-p2.x, cy=p3.y-p2.y, cz=p3.z-p2.z;
        float ia = 1.f/fmaxf(sqrtf(ax*ax+ay*ay+az*az), 1e-12f); ax*=ia; ay*=ia; az*=ia;
        float ib = 1.f/fmaxf(sqrtf(bx*bx+by*by+bz*bz), 1e-12f); bx*=ib; by*=ib; bz*=ib;
        float ic = 1.f/fmaxf(sqrtf(cx*cx+cy*cy+cz*cz), 1e-12f); cx*=ic; cy*=ic; cz*=ic;
        float n2x=ay*bz-az*by, n2y=az*bx-ax*bz, n2z=ax*by-ay*bx;
        float n1x=by*cz-bz*cy, n1y=bz*cx-bx*cz, n1z=bx*cy-by*cx;
        float i2 = 1.f/fmaxf(sqrtf(n2x*n2x+n2y*n2y+n2z*n2z), 1e-12f); n2x*=i2; n2y*=i2; n2z*=i2;
        float i1 = 1.f/fmaxf(sqrtf(n1x*n1x+n1y*n1y+n1z*n1z), 1e-12f); n1x*=i1; n1y*=i1; n1z*=i1;
        float cosA = -(bx*cx+by*cy+bz*cz);
        cosA = fminf(fmaxf(cosA, -1.f+1e-6f), 1.f-1e-6f);
        float cosD = n2x*n1x+n2y*n1y+n2z*n1z;
        cosD = fminf(fmaxf(cosD, -1.f+1e-6f), 1.f-1e-6f);
        float sgn = signf_(ax*n1x+ay*n1y+az*n1z);
        float sA = sqrtf(fmaxf(1.f-cosA*cosA, 0.f));
        float sD = sgn*sqrtf(fmaxf(1.f-cosD*cosD, 0.f));
        ad0 = cosA;
        ad1 = sA*cosD;
        ad2 = sA*sD;
    }
    float h[4];
    #pragma unroll
    for (int i=0;i<4;i++){
        int c = lane + 32*i;
        h[i] = b_node[c] + ad0*W_node[c] + ad1*W_node[128+c] + ad2*W_node[256+c];
    }
    float s = h[0]+h[1]+h[2]+h[3];
    #pragma unroll
    for (int off=16;off;off>>=1) s += __shfl_xor_sync(0xffffffffu, s, off);
    float mu = s * (1.f/128.f);
    float d0=h[0]-mu, d1=h[1]-mu, d2=h[2]-mu, d3=h[3]-mu;
    float ss = d0*d0+d1*d1+d2*d2+d3*d3;
    #pragma unroll
    for (int off=16;off;off>>=1) ss += __shfl_xor_sync(0xffffffffu, ss, off);
    float invr = 1.f/sqrtf(ss*(1.f/128.f) + 1e-5f);
    size_t base = (size_t)gw*128;
    #pragma unroll
    for (int i=0;i<4;i++){
        int c = lane + 32*i;
        outV[base + c] = (h[i]-mu)*invr*gN[c] + bnN[c];
    }
}

// ---------------- kernel 4: fused edge features + GEMM + LN -----------------
// block = 256 threads, 64 edges. Phase 1: threads 0-63 compute 23 features into
// transposed shared sFt[r][edge]; all threads pre-pack broadcast weights.
// Phase 2: warp = 8 edges as 4 f32x2 edge-pairs, lane owns channels [4c,4c+4).
__global__ void k_edge(const int* __restrict__ resid, const int* __restrict__ chain,
                       const float* __restrict__ b_edge, const float* __restrict__ gE,
                       const float* __restrict__ bnE, float* __restrict__ outE){
    __shared__ unsigned long long sWp[23*128];  // (w,w) broadcast pairs
    __shared__ float sFt[23][64];               // feature-major, edge minor
    __shared__ int   sCls[64];
    int tid = threadIdx.x;
    int e0 = blockIdx.x * 64;

    for (int i = tid; i < 23*128; i += 256){
        float w = g_W2r[i];
        unsigned long long w2; PACK2(w2, w, w);
        sWp[i] = w2;
    }
    if (tid < 64){
        int e = e0 + tid;
        int n = e / TOPK;
        int b = n >> 11;
        int j = g_Eidx[e];
        int nj = (b<<11) + j;
        float D = g_Dnb[e];
        #pragma unroll
        for (int m=0;m<16;m++){
            float mu = 2.0f + (float)m*(20.0f/15.0f);
            float t = (D - mu)*0.8f;
            sFt[m][tid] = expf(-t*t);
        }
        float4 a1=g_E1[n],  a2=g_E2[n],  a3=g_E3[n];
        float4 c1=g_E1[nj], c2=g_E2[nj], c3=g_E3[nj];
        float4 pi=g_CaP[n], pj=g_CaP[nj];
        float dx=pj.x-pi.x, dy=pj.y-pi.y, dz=pj.z-pi.z;
        float ux = a1.x*dx + a2.x*dy + a3.x*dz;
        float uy = a1.y*dx + a2.y*dy + a3.y*dz;
        float uz = a1.z*dx + a2.z*dy + a3.z*dz;
        float iu = 1.f/fmaxf(sqrtf(ux*ux+uy*uy+uz*uz), 1e-12f);
        sFt[16][tid]=ux*iu; sFt[17][tid]=uy*iu; sFt[18][tid]=uz*iu;
        float R00=a1.x*c1.x+a1.y*c1.y+a1.z*c1.z;
        float R01=a1.x*c2.x+a1.y*c2.y+a1.z*c2.z;
        float R02=a1.x*c3.x+a1.y*c3.y+a1.z*c3.z;
        float R10=a2.x*c1.x+a2.y*c1.y+a2.z*c1.z;
        float R11=a2.x*c2.x+a2.y*c2.y+a2.z*c2.z;
        float R12=a2.x*c3.x+a2.y*c3.y+a2.z*c3.z;
        float R20=a3.x*c1.x+a3.y*c1.y+a3.z*c1.z;
        float R21=a3.x*c2.x+a3.y*c2.y+a3.z*c2.z;
        float R22=a3.x*c3.x+a3.y*c3.y+a3.z*c3.z;
        float m0 = 0.5f*sqrtf(fabsf(1.f + R00 - R11 - R22));
        float m1 = 0.5f*sqrtf(fabsf(1.f - R00 + R11 - R22));
        float m2 = 0.5f*sqrtf(fabsf(1.f - R00 - R11 + R22));
        float qx = signf_(R21 - R12)*m0;
        float qy = signf_(R02 - R20)*m1;
        float qz = signf_(R10 - R01)*m2;
        float qw = 0.5f*sqrtf(fmaxf(1.f + R00 + R11 + R22, 0.f));
        float iq = 1.f/fmaxf(sqrtf(qx*qx+qy*qy+qz*qz+qw*qw), 1e-12f);
        sFt[19][tid]=qx*iq; sFt[20][tid]=qy*iq; sFt[21][tid]=qz*iq; sFt[22][tid]=qw*iq;
        int off = resid[nj] - resid[n];
        int dcl = min(max(off + 32, 0), 64);
        int s   = (chain[nj]==chain[n]) ? 0 : 1;
        sCls[tid] = dcl | (s<<8);
    }
    __syncthreads();

    int wrp = tid >> 5, cg = tid & 31;
    int ebase = wrp * 8;
    int c0 = cg * 4;
    float4 bv = *(const float4*)(b_edge + c0);

    unsigned long long acc[4][4];   // [edge-pair][channel]
    #pragma unroll
    for (int pp=0;pp<4;pp++){
        int ea = ebase + 2*pp, eb = ea + 1;
        int ca = sCls[ea], cb = sCls[eb];
        float4 peA = *(const float4*)(g_Ppe + (ca&255)*128 + c0);
        float4 pcA = *(const float4*)(g_Pch + (ca>>8)*128 + c0);
        float4 peB = *(const float4*)(g_Ppe + (cb&255)*128 + c0);
        float4 pcB = *(const float4*)(g_Pch + (cb>>8)*128 + c0);
        PACK2(acc[pp][0], bv.x+peA.x+pcA.x, bv.x+peB.x+pcB.x);
        PACK2(acc[pp][1], bv.y+peA.y+pcA.y, bv.y+peB.y+pcB.y);
        PACK2(acc[pp][2], bv.z+peA.z+pcA.z, bv.z+peB.z+pcB.z);
        PACK2(acc[pp][3], bv.w+peA.w+pcA.w, bv.w+peB.w+pcB.w);
    }
    #pragma unroll
    for (int r=0;r<23;r++){
        ulonglong2 wA = *(const ulonglong2*)(sWp + r*128 + c0);
        ulonglong2 wB = *(const ulonglong2*)(sWp + r*128 + c0 + 2);
        #pragma unroll
        for (int pp=0;pp<4;pp++){
            unsigned long long f2 = *(const unsigned long long*)(&sFt[r][ebase + 2*pp]);
            FMA2(acc[pp][0], f2, wA.x, acc[pp][0]);
            FMA2(acc[pp][1], f2, wA.y, acc[pp][1]);
            FMA2(acc[pp][2], f2, wB.x, acc[pp][2]);
            FMA2(acc[pp][3], f2, wB.y, acc[pp][3]);
        }
    }
    float4 ge = *(const float4*)(gE + c0);
    float4 be = *(const float4*)(bnE + c0);
    unsigned long long cM, cV;
    PACK2(cM, -0.0078125f, -0.0078125f);   // -1/128
    #pragma unroll
    for (int pp=0;pp<4;pp++){
        unsigned long long s2 = acc[pp][0];
        ADD2(s2, s2, acc[pp][1]);
        ADD2(s2, s2, acc[pp][2]);
        ADD2(s2, s2, acc[pp][3]);
        #pragma unroll
        for (int off=16;off;off>>=1){
            unsigned long long o = __shfl_xor_sync(0xffffffffu, s2, off);
            ADD2(s2, s2, o);
        }
        unsigned long long nmu2; MUL2(nmu2, s2, cM);   // (-mu, -mu')
        unsigned long long dd[4];
        ADD2(dd[0], acc[pp][0], nmu2);
        ADD2(dd[1], acc[pp][1], nmu2);
        ADD2(dd[2], acc[pp][2], nmu2);
        ADD2(dd[3], acc[pp][3], nmu2);
        unsigned long long ss2; PACK2(ss2, 0.f, 0.f);
        FMA2(ss2, dd[0], dd[0], ss2);
        FMA2(ss2, dd[1], dd[1], ss2);
        FMA2(ss2, dd[2], dd[2], ss2);
        FMA2(ss2, dd[3], dd[3], ss2);
        #pragma unroll
        for (int off=16;off;off>>=1){
            unsigned long long o = __shfl_xor_sync(0xffffffffu, ss2, off);
            ADD2(ss2, ss2, o);
        }
        float ssa, ssb; UNPK2(ssa, ssb, ss2);
        float ira = 1.f/sqrtf(ssa*(1.f/128.f) + 1e-5f);
        float irb = 1.f/sqrtf(ssb*(1.f/128.f) + 1e-5f);
        float d0a,d0b,d1a,d1b,d2a,d2b,d3a,d3b;
        UNPK2(d0a,d0b,dd[0]); UNPK2(d1a,d1b,dd[1]);
        UNPK2(d2a,d2b,dd[2]); UNPK2(d3a,d3b,dd[3]);
        int ea = e0 + ebase + 2*pp;
        float4 oA, oB;
        oA.x = d0a*ira*ge.x + be.x;  oB.x = d0b*irb*ge.x + be.x;
        oA.y = d1a*ira*ge.y + be.y;  oB.y = d1b*irb*ge.y + be.y;
        oA.z = d2a*ira*ge.z + be.z;  oB.z = d2b*irb*ge.z + be.z;
        oA.w = d3a*ira*ge.w + be.w;  oB.w = d3b*irb*ge.w + be.w;
        *(float4*)(outE + (size_t)ea*128 + c0)       = oA;
        *(float4*)(outE + (size_t)(ea+1)*128 + c0)   = oB;
    }
}

// ---------------- launch ----------------------------------------------------
extern "C" void kernel_launch(void* const* d_in, const int* in_sizes, int n_in,
                              void* d_out, int out_size){
    const float* X        = (const float*)d_in[0];
    const int*   resid    = (const int*)  d_in[2];
    const int*   chain    = (const int*)  d_in[3];
    const float* W_pe     = (const float*)d_in[4];
    const float* b_pe     = (const float*)d_in[5];
    const float* W_ch     = (const float*)d_in[6];
    const float* b_ch     = (const float*)d_in[7];
    const float* W_node   = (const float*)d_in[8];
    const float* b_node   = (const float*)d_in[9];
    const float* W_edge   = (const float*)d_in[10];
    const float* b_edge   = (const float*)d_in[11];
    const float* g_nodes  = (const float*)d_in[12];
    const float* bn_nodes = (const float*)d_in[13];
    const float* g_edges  = (const float*)d_in[14];
    const float* bn_edges = (const float*)d_in[15];

    float* out  = (float*)d_out;
    float* outV = out;
    float* outE = out + (size_t)NODES*128;
    float* outI = out + (size_t)NODES*128 + (size_t)NEDGE*128;

    k_prep <<<77, 256>>>(X, W_pe, b_pe, W_ch, b_ch, W_edge);
    k_topk <<<NODES, 512>>>(outI);
    k_node <<<NODES/8, 256>>>(W_node, b_node, g_nodes, bn_nodes, outV);
    k_edge <<<NEDGE/64, 256>>>(resid, chain, b_edge, g_edges, bn_edges, outE);
}

// round 4
// speedup vs baseline: 3.5819x; 3.5819x over previous
#include <cuda_runtime.h>
#include <cfloat>
#include <math.h>

#define BB   4
#define LL   2048
#define NODES (BB*LL)            // 8192
#define TOPK 30
#define NEDGE (NODES*TOPK)       // 245760
#define NTILE (NEDGE/64)         // 3840

// ---------------- scratch ----------------------------------------------------
__device__ float4 g_CaP[NODES];
__device__ float4 g_E1[NODES];
__device__ float4 g_E2[NODES];
__device__ float4 g_E3[NODES];
__device__ float  g_Dnb[NEDGE];
__device__ int    g_Eidx[NEDGE];
__device__ float  g_Feat[NTILE*24*64];     // transposed: [tile][feature][edge-in-tile]
__device__ float  g_Ppe[65*128];           // (W_pe+b_pe) @ W_edge[0:16]
__device__ float  g_Pch[2*128];            // (W_ch+b_ch) @ W_edge[39:55]
__device__ float  g_W2r[23*128];           // W_edge rows [16:39)

__device__ __forceinline__ float signf_(float x){ return (x>0.f)?1.f:((x<0.f)?-1.f:0.f); }

#define FMA2(d,a,b,c) asm("fma.rn.f32x2 %0,%1,%2,%3;" : "=l"(d) : "l"(a), "l"(b), "l"(c))
#define ADD2(d,a,b)   asm("add.rn.f32x2 %0,%1,%2;"    : "=l"(d) : "l"(a), "l"(b))
#define MUL2(d,a,b)   asm("mul.rn.f32x2 %0,%1,%2;"    : "=l"(d) : "l"(a), "l"(b))
#define PACK2(d,lo,hi) asm("mov.b64 %0,{%1,%2};" : "=l"(d) : "f"(lo), "f"(hi))
#define UNPK2(lo,hi,s) asm("mov.b64 {%0,%1},%2;" : "=f"(lo), "=f"(hi) : "l"(s))

// ---------------- kernel 1: prep (pack frames + projection tables) ----------
__global__ void k_prep(const float* __restrict__ X,
                       const float* __restrict__ W_pe, const float* __restrict__ b_pe,
                       const float* __restrict__ W_ch, const float* __restrict__ b_ch,
                       const float* __restrict__ W_edge){
    int blk = blockIdx.x;
    if (blk < 32){
        int n = blk*256 + threadIdx.x;
        const float* p = X + (size_t)n*12;
        float Nx=p[0], Ny=p[1], Nz=p[2];
        float Cx=p[3], Cy=p[4], Cz=p[5];
        float Dx=p[6], Dy=p[7], Dz=p[8];
        g_CaP[n] = make_float4(Cx,Cy,Cz,0.f);
        float v1x=Nx-Cx, v1y=Ny-Cy, v1z=Nz-Cz;
        float v2x=Dx-Cx, v2y=Dy-Cy, v2z=Dz-Cz;
        float n1 = sqrtf(v1x*v1x+v1y*v1y+v1z*v1z);
        float i1 = 1.f/(n1+1e-6f);
        float e1x=v1x*i1, e1y=v1y*i1, e1z=v1z*i1;
        float dv = e1x*v2x+e1y*v2y+e1z*v2z;
        float u2x=v2x-dv*e1x, u2y=v2y-dv*e1y, u2z=v2z-dv*e1z;
        float n2 = sqrtf(u2x*u2x+u2y*u2y+u2z*u2z);
        float i2 = 1.f/(n2+1e-6f);
        float e2x=u2x*i2, e2y=u2y*i2, e2z=u2z*i2;
        g_E1[n] = make_float4(e1x,e1y,e1z,0.f);
        g_E2[n] = make_float4(e2x,e2y,e2z,0.f);
        g_E3[n] = make_float4(e1y*e2z-e1z*e2y, e1z*e2x-e1x*e2z, e1x*e2y-e1y*e2x, 0.f);
    } else {
        int idx = (blk-32)*256 + threadIdx.x;
        if (idx < 65*128){
            int r = idx >> 7, c = idx & 127;
            float s = 0.f;
            #pragma unroll
            for (int m=0;m<16;m++) s += (W_pe[r*16+m]+b_pe[m]) * W_edge[m*128+c];
            g_Ppe[idx] = s;
        } else if (idx < 65*128 + 2*128){
            int t = idx - 65*128; int r = t >> 7, c = t & 127;
            float s = 0.f;
            #pragma unroll
            for (int m=0;m<16;m++) s += (W_ch[r*16+m]+b_ch[m]) * W_edge[(39+m)*128+c];
            g_Pch[t] = s;
        } else if (idx < 65*128 + 2*128 + 23*128){
            int t = idx - (65*128+2*128); int r = t >> 7, c = t & 127;
            int row = (r < 16) ? (16+r) : (32 + (r-16));
            g_W2r[t] = W_edge[row*128+c];
        }
    }
}

// ---------------- kernel 2: top-30 per row via radix select (R2 version) ----
__global__ void k_topk(float* __restrict__ outIdxF){
    __shared__ unsigned sK[2048];
    __shared__ unsigned sCnt[256];
    __shared__ unsigned sTieJ[256];
    __shared__ unsigned sWinK[32];
    __shared__ unsigned sWinJ[32];
    __shared__ unsigned sCtl[4];   // 0: prefix, 1: base, 2: cntL, 3: cntE

    int row = blockIdx.x;
    int b   = row >> 11;
    int tid = threadIdx.x;
    float4 p = g_CaP[row];

    #pragma unroll
    for (int u=0;u<8;u++){
        int j = tid + (u<<8);
        float4 q = g_CaP[(b<<11)+j];
        float dx=q.x-p.x, dy=q.y-p.y, dz=q.z-p.z;
        float s = __fadd_rn(__fadd_rn(__fmul_rn(dx,dx),__fmul_rn(dy,dy)),__fmul_rn(dz,dz));
        float D = __fsqrt_rn(__fadd_rn(s, 1e-6f));
        sK[j] = __float_as_uint(D);
    }
    if (tid < 4) sCtl[tid] = 0;
    __syncthreads();

    #pragma unroll
    for (int pass=0; pass<4; pass++){
        int shift = 24 - 8*pass;
        sCnt[tid] = 0;
        __syncthreads();
        unsigned pref = sCtl[0];
        #pragma unroll
        for (int u=0;u<8;u++){
            unsigned k = sK[tid + (u<<8)];
            if ( ((unsigned long long)(k ^ pref) >> (shift+8)) == 0ULL )
                atomicAdd(&sCnt[(k>>shift)&255u], 1u);
        }
        __syncthreads();
        if (tid < 32){
            unsigned c[8]; unsigned s = 0;
            #pragma unroll
            for (int i=0;i<8;i++){ c[i] = sCnt[tid*8+i]; s += c[i]; }
            unsigned incl = s;
            #pragma unroll
            for (int off=1; off<32; off<<=1){
                unsigned v = __shfl_up_sync(0xffffffffu, incl, off);
                if (tid >= off) incl += v;
            }
            unsigned excl = incl - s;
            unsigned base = sCtl[1];
            unsigned need = 29u - base;
            if (need >= excl && need < incl){
                unsigned acc = excl; int bsel = -1; unsigned basebin = excl;
                #pragma unroll
                for (int i=0;i<8;i++){
                    if (bsel < 0){
                        if (need < acc + c[i]) { bsel = i; basebin = acc; }
                        else acc += c[i];
                    }
                }
                sCtl[0] = pref | ((unsigned)(tid*8 + bsel) << shift);
                sCtl[1] = base + basebin;
            }
        }
        __syncthreads();
    }

    unsigned P = sCtl[0];
    #pragma unroll
    for (int u=0;u<8;u++){
        int j = tid + (u<<8);
        unsigned k = sK[j];
        if (k < P){
            unsigned pos = atomicAdd(&sCtl[2], 1u);
            sWinK[pos] = k; sWinJ[pos] = (unsigned)j;
        } else if (k == P){
            unsigned pos = atomicAdd(&sCtl[3], 1u);
            if (pos < 256) sTieJ[pos] = (unsigned)j;
        }
    }
    __syncthreads();
    unsigned cntL = sCtl[2];
    unsigned cntE = sCtl[3];
    unsigned needE = 30u - cntL;
    if (tid < (int)cntE && tid < 256){
        unsigned myj = sTieJ[tid];
        unsigned r = 0;
        unsigned lim = (cntE < 256u) ? cntE : 256u;
        for (unsigned i=0;i<lim;i++) r += (sTieJ[i] < myj) ? 1u : 0u;
        if (r < needE){ sWinK[cntL + r] = P; sWinJ[cntL + r] = myj; }
    }
    __syncthreads();
    unsigned mk=0, mj=0, rk=0;
    if (tid < (int)cntL){
        mk = sWinK[tid]; mj = sWinJ[tid];
        for (unsigned i=0;i<cntL;i++){
            unsigned ok = sWinK[i], oj = sWinJ[i];
            rk += ((ok < mk) || (ok == mk && oj < mj)) ? 1u : 0u;
        }
    }
    __syncthreads();
    if (tid < (int)cntL){ sWinK[rk] = mk; sWinJ[rk] = mj; }
    __syncthreads();
    if (tid < TOPK){
        int e = row*TOPK + tid;
        unsigned j = sWinJ[tid];
        g_Eidx[e]  = (int)j;
        g_Dnb[e]   = __uint_as_float(sWinK[tid]);
        outIdxF[e] = (float)j;
    }
}

// ---------------- kernel 3: node dihedral features + LN (trig-free) ---------
__global__ void k_node(const float* __restrict__ W_node, const float* __restrict__ b_node,
                       const float* __restrict__ gN, const float* __restrict__ bnN,
                       float* __restrict__ outV){
    int gw   = (blockIdx.x*blockDim.x + threadIdx.x) >> 5;
    int lane = threadIdx.x & 31;
    if (gw >= NODES) return;
    int l = gw & 2047;

    float ad0=0.f, ad1=0.f, ad2=0.f;
    if (l >= 1 && l <= LL-3){
        float4 p0=g_CaP[gw-1], p1=g_CaP[gw], p2=g_CaP[gw+1], p3=g_CaP[gw+2];
        float ax=p1.x-p0.x, ay=p1.y-p0.y, az=p1.z-p0.z;
        float bx=p2.x-p1.x, by=p2.y-p1.y, bz=p2.z-p1.z;
        float cx=p3.x-p2.x, cy=p3.y-p2.y, cz=p3.z-p2.z;
        float ia = 1.f/fmaxf(sqrtf(ax*ax+ay*ay+az*az), 1e-12f); ax*=ia; ay*=ia; az*=ia;
        float ib = 1.f/fmaxf(sqrtf(bx*bx+by*by+bz*bz), 1e-12f); bx*=ib; by*=ib; bz*=ib;
        float ic = 1.f/fmaxf(sqrtf(cx*cx+cy*cy+cz*cz), 1e-12f); cx*=ic; cy*=ic; cz*=ic;
        float n2x=ay*bz-az*by, n2y=az*bx-ax*bz, n2z=ax*by-ay*bx;
        float n1x=by*cz-bz*cy, n1y=bz*cx-bx*cz, n1z=bx*cy-by*cx;
        float i2 = 1.f/fmaxf(sqrtf(n2x*n2x+n2y*n2y+n2z*n2z), 1e-12f); n2x*=i2; n2y*=i2; n2z*=i2;
        float i1 = 1.f/fmaxf(sqrtf(n1x*n1x+n1y*n1y+n1z*n1z), 1e-12f); n1x*=i1; n1y*=i1; n1z*=i1;
        float cosA = -(bx*cx+by*cy+bz*cz);
        cosA = fminf(fmaxf(cosA, -1.f+1e-6f), 1.f-1e-6f);
        float cosD = n2x*n1x+n2y*n1y+n2z*n1z;
        cosD = fminf(fmaxf(cosD, -1.f+1e-6f), 1.f-1e-6f);
        float sgn = signf_(ax*n1x+ay*n1y+az*n1z);
        float sA = sqrtf(fmaxf(1.f-cosA*cosA, 0.f));
        float sD = sgn*sqrtf(fmaxf(1.f-cosD*cosD, 0.f));
        ad0 = cosA;
        ad1 = sA*cosD;
        ad2 = sA*sD;
    }
    float h[4];
    #pragma unroll
    for (int i=0;i<4;i++){
        int c = lane + 32*i;
        h[i] = b_node[c] + ad0*W_node[c] + ad1*W_node[128+c] + ad2*W_node[256+c];
    }
    float s = h[0]+h[1]+h[2]+h[3];
    #pragma unroll
    for (int off=16;off;off>>=1) s += __shfl_xor_sync(0xffffffffu, s, off);
    float mu = s * (1.f/128.f);
    float d0=h[0]-mu, d1=h[1]-mu, d2=h[2]-mu, d3=h[3]-mu;
    float ss = d0*d0+d1*d1+d2*d2+d3*d3;
    #pragma unroll
    for (int off=16;off;off>>=1) ss += __shfl_xor_sync(0xffffffffu, ss, off);
    float invr = 1.f/sqrtf(ss*(1.f/128.f) + 1e-5f);
    size_t base = (size_t)gw*128;
    #pragma unroll
    for (int i=0;i<4;i++){
        int c = lane + 32*i;
        outV[base + c] = (h[i]-mu)*invr*gN[c] + bnN[c];
    }
}

// ---------------- kernel 4: per-edge features (transposed tile store) -------
__global__ void k_efeat(const int* __restrict__ resid, const int* __restrict__ chain){
    int e = blockIdx.x*blockDim.x + threadIdx.x;
    if (e >= NEDGE) return;
    int n = e / TOPK;
    int b = n >> 11;
    int j = g_Eidx[e];
    int nj = (b<<11) + j;
    int tile = e >> 6, sub = e & 63;
    float* f = g_Feat + (size_t)tile*1536 + sub;   // stride-64 writes, warp-coalesced

    float D = g_Dnb[e];
    #pragma unroll
    for (int m=0;m<16;m++){
        float mu = 2.0f + (float)m*(20.0f/15.0f);
        float t = (D - mu)*0.8f;
        f[m*64] = expf(-t*t);
    }
    float4 a1=g_E1[n],  a2=g_E2[n],  a3=g_E3[n];
    float4 c1=g_E1[nj], c2=g_E2[nj], c3=g_E3[nj];
    float4 pi=g_CaP[n], pj=g_CaP[nj];
    float dx=pj.x-pi.x, dy=pj.y-pi.y, dz=pj.z-pi.z;
    float ux = a1.x*dx + a2.x*dy + a3.x*dz;
    float uy = a1.y*dx + a2.y*dy + a3.y*dz;
    float uz = a1.z*dx + a2.z*dy + a3.z*dz;
    float iu = 1.f/fmaxf(sqrtf(ux*ux+uy*uy+uz*uz), 1e-12f);
    f[16*64]=ux*iu; f[17*64]=uy*iu; f[18*64]=uz*iu;
    float R00=a1.x*c1.x+a1.y*c1.y+a1.z*c1.z;
    float R01=a1.x*c2.x+a1.y*c2.y+a1.z*c2.z;
    float R02=a1.x*c3.x+a1.y*c3.y+a1.z*c3.z;
    float R10=a2.x*c1.x+a2.y*c1.y+a2.z*c1.z;
    float R11=a2.x*c2.x+a2.y*c2.y+a2.z*c2.z;
    float R12=a2.x*c3.x+a2.y*c3.y+a2.z*c3.z;
    float R20=a3.x*c1.x+a3.y*c1.y+a3.z*c1.z;
    float R21=a3.x*c2.x+a3.y*c2.y+a3.z*c2.z;
    float R22=a3.x*c3.x+a3.y*c3.y+a3.z*c3.z;
    float m0 = 0.5f*sqrtf(fabsf(1.f + R00 - R11 - R22));
    float m1 = 0.5f*sqrtf(fabsf(1.f - R00 + R11 - R22));
    float m2 = 0.5f*sqrtf(fabsf(1.f - R00 - R11 + R22));
    float qx = signf_(R21 - R12)*m0;
    float qy = signf_(R02 - R20)*m1;
    float qz = signf_(R10 - R01)*m2;
    float qw = 0.5f*sqrtf(fmaxf(1.f + R00 + R11 + R22, 0.f));
    float iq = 1.f/fmaxf(sqrtf(qx*qx+qy*qy+qz*qz+qw*qw), 1e-12f);
    f[19*64]=qx*iq; f[20*64]=qy*iq; f[21*64]=qz*iq; f[22*64]=qw*iq;
    int off = resid[nj] - resid[n];
    int dcl = min(max(off + 32, 0), 64);
    int s   = (chain[nj]==chain[n]) ? 0 : 1;
    f[23*64] = __int_as_float(dcl | (s<<8));
}

// ---------------- kernel 5: edge GEMM (edge-pair f32x2) + LN ----------------
// block 256 threads = 8 warps; warp = 8 edges (4 pairs); lane owns channels [4c,4c+4)
__global__ void k_egemm(const float* __restrict__ b_edge, const float* __restrict__ gE,
                        const float* __restrict__ bnE, float* __restrict__ outE){
    __shared__ float sW[23*128];     // scalar weights
    __shared__ float sFt[24][64];    // feature-major tile
    int tid = threadIdx.x;
    int e0 = blockIdx.x * 64;

    for (int i = tid; i < 23*128; i += 256) sW[i] = g_W2r[i];
    {
        const float4* src = (const float4*)(g_Feat + (size_t)blockIdx.x*1536);
        float4* dst = (float4*)&sFt[0][0];
        dst[tid] = src[tid];
        if (tid < 128) dst[tid+256] = src[tid+256];
    }
    __syncthreads();

    int wrp = tid >> 5, cg = tid & 31;
    int ebase = wrp * 8;
    int c0 = cg * 4;
    float4 bv = *(const float4*)(b_edge + c0);

    unsigned long long acc[4][4];   // [edge-pair][channel] = (edgeA, edgeB)
    #pragma unroll
    for (int pp=0;pp<4;pp++){
        int ea = ebase + 2*pp, eb = ea + 1;
        int ca = __float_as_int(sFt[23][ea]);
        int cb = __float_as_int(sFt[23][eb]);
        float4 peA = *(const float4*)(g_Ppe + (ca&255)*128 + c0);
        float4 pcA = *(const float4*)(g_Pch + (ca>>8)*128 + c0);
        float4 peB = *(const float4*)(g_Ppe + (cb&255)*128 + c0);
        float4 pcB = *(const float4*)(g_Pch + (cb>>8)*128 + c0);
        PACK2(acc[pp][0], bv.x+peA.x+pcA.x, bv.x+peB.x+pcB.x);
        PACK2(acc[pp][1], bv.y+peA.y+pcA.y, bv.y+peB.y+pcB.y);
        PACK2(acc[pp][2], bv.z+peA.z+pcA.z, bv.z+peB.z+pcB.z);
        PACK2(acc[pp][3], bv.w+peA.w+pcA.w, bv.w+peB.w+pcB.w);
    }
    #pragma unroll
    for (int r=0;r<23;r++){
        float4 w4 = *(const float4*)(sW + r*128 + c0);
        unsigned long long w0,w1,w2,w3;
        PACK2(w0, w4.x, w4.x); PACK2(w1, w4.y, w4.y);
        PACK2(w2, w4.z, w4.z); PACK2(w3, w4.w, w4.w);
        #pragma unroll
        for (int pp=0;pp<4;pp++){
            unsigned long long f2 = *(const unsigned long long*)(&sFt[r][ebase + 2*pp]);
            FMA2(acc[pp][0], f2, w0, acc[pp][0]);
            FMA2(acc[pp][1], f2, w1, acc[pp][1]);
            FMA2(acc[pp][2], f2, w2, acc[pp][2]);
            FMA2(acc[pp][3], f2, w3, acc[pp][3]);
        }
    }
    float4 ge = *(const float4*)(gE + c0);
    float4 be = *(const float4*)(bnE + c0);
    unsigned long long cM;
    PACK2(cM, -0.0078125f, -0.0078125f);   // -1/128
    #pragma unroll
    for (int pp=0;pp<4;pp++){
        unsigned long long s2 = acc[pp][0];
        ADD2(s2, s2, acc[pp][1]);
        ADD2(s2, s2, acc[pp][2]);
        ADD2(s2, s2, acc[pp][3]);
        #pragma unroll
        for (int off=16;off;off>>=1){
            unsigned long long o = __shfl_xor_sync(0xffffffffu, s2, off);
            ADD2(s2, s2, o);
        }
        unsigned long long nmu2; MUL2(nmu2, s2, cM);
        unsigned long long dd[4];
        ADD2(dd[0], acc[pp][0], nmu2);
        ADD2(dd[1], acc[pp][1], nmu2);
        ADD2(dd[2], acc[pp][2], nmu2);
        ADD2(dd[3], acc[pp][3], nmu2);
        unsigned long long ss2; PACK2(ss2, 0.f, 0.f);
        FMA2(ss2, dd[0], dd[0], ss2);
        FMA2(ss2, dd[1], dd[1], ss2);
        FMA2(ss2, dd[2], dd[2], ss2);
        FMA2(ss2, dd[3], dd[3], ss2);
        #pragma unroll
        for (int off=16;off;off>>=1){
            unsigned long long o = __shfl_xor_sync(0xffffffffu, ss2, off);
            ADD2(ss2, ss2, o);
        }
        float ssa, ssb; UNPK2(ssa, ssb, ss2);
        float ira = 1.f/sqrtf(ssa*(1.f/128.f) + 1e-5f);
        float irb = 1.f/sqrtf(ssb*(1.f/128.f) + 1e-5f);
        float d0a,d0b,d1a,d1b,d2a,d2b,d3a,d3b;
        UNPK2(d0a,d0b,dd[0]); UNPK2(d1a,d1b,dd[1]);
        UNPK2(d2a,d2b,dd[2]); UNPK2(d3a,d3b,dd[3]);
        int ea = e0 + ebase + 2*pp;
        float4 oA, oB;
        oA.x = d0a*ira*ge.x + be.x;  oB.x = d0b*irb*ge.x + be.x;
        oA.y = d1a*ira*ge.y + be.y;  oB.y = d1b*irb*ge.y + be.y;
        oA.z = d2a*ira*ge.z + be.z;  oB.z = d2b*irb*ge.z + be.z;
        oA.w = d3a*ira*ge.w + be.w;  oB.w = d3b*irb*ge.w + be.w;
        *(float4*)(outE + (size_t)ea*128 + c0)     = oA;
        *(float4*)(outE + (size_t)(ea+1)*128 + c0) = oB;
    }
}

// ---------------- launch ----------------------------------------------------
extern "C" void kernel_launch(void* const* d_in, const int* in_sizes, int n_in,
                              void* d_out, int out_size){
    const float* X        = (const float*)d_in[0];
    const int*   resid    = (const int*)  d_in[2];
    const int*   chain    = (const int*)  d_in[3];
    const float* W_pe     = (const float*)d_in[4];
    const float* b_pe     = (const float*)d_in[5];
    const float* W_ch     = (const float*)d_in[6];
    const float* b_ch     = (const float*)d_in[7];
    const float* W_node   = (const float*)d_in[8];
    const float* b_node   = (const float*)d_in[9];
    const float* W_edge   = (const float*)d_in[10];
    const float* b_edge   = (const float*)d_in[11];
    const float* g_nodes  = (const float*)d_in[12];
    const float* bn_nodes = (const float*)d_in[13];
    const float* g_edges  = (const float*)d_in[14];
    const float* bn_edges = (const float*)d_in[15];

    float* out  = (float*)d_out;
    float* outV = out;
    float* outE = out + (size_t)NODES*128;
    float* outI = out + (size_t)NODES*128 + (size_t)NEDGE*128;

    k_prep <<<77, 256>>>(X, W_pe, b_pe, W_ch, b_ch, W_edge);
    k_topk <<<NODES, 256>>>(outI);
    k_node <<<NODES/8, 256>>>(W_node, b_node, g_nodes, bn_nodes, outV);
    k_efeat<<<(NEDGE+255)/256, 256>>>(resid, chain);
    k_egemm<<<NTILE, 256>>>(b_edge, g_edges, bn_edges, outE);
}